// round 16
// baseline (speedup 1.0000x reference)
#include <cuda_runtime.h>
#include <cstdint>

// ---------------------------------------------------------------------------
// ContourRec: 2-level contourlet DFB reconstruction (4 subbands).
// Stage A (fbrec '2c','per'): NEW 2-CTA-cluster kernel, each CTA owns 64 rows
//   of A/B/C -> smem 109.9KB -> 2 CTAs/SM (100% occ). Halo rows for the
//   column conv staged from peer via DSMEM. qprec '2c' partitioned so each
//   CTA writes a contiguous 128-col window per output row from LOCAL rows.
// Stage B (fbrec '1r','qper_col') + qprec '1r': EXACT R13 4-CTA-cluster
//   kernel (67.0us) — untouched.
// ---------------------------------------------------------------------------

#define PA 132
#define INV_SQRT2 0.70710678118654752f
#define SQRT2     1.41421356237309505f

__device__ float g_x[16777216];     // 8*64*128*256 (stage-A output)

#define DEF_FILT const float FILT[12] = {0.0144f, 0.0272f, 0.0526f, 0.0972f, \
    0.193f, 0.63f, -0.63f, -0.193f, -0.0972f, -0.0526f, -0.0272f, -0.0144f}

__device__ __forceinline__ float4 f4fma(float s, float4 v, float4 a) {
    a.x = fmaf(s, v.x, a.x); a.y = fmaf(s, v.y, a.y);
    a.z = fmaf(s, v.z, a.z); a.w = fmaf(s, v.w, a.w);
    return a;
}

__device__ __forceinline__ uint32_t smem_u32(const void* p) {
    uint32_t a;
    asm("{ .reg .u64 t; cvta.to.shared.u64 t, %1; cvt.u32.u64 %0, t; }"
        : "=r"(a) : "l"(p));
    return a;
}
__device__ __forceinline__ uint32_t mapa_rank(uint32_t addr, uint32_t rank) {
    uint32_t r;
    asm("mapa.shared::cluster.u32 %0, %1, %2;" : "=r"(r) : "r"(addr), "r"(rank));
    return r;
}
__device__ __forceinline__ float ld_dsm(uint32_t addr) {
    float v;
    asm volatile("ld.shared::cluster.f32 %0, [%1];" : "=f"(v) : "r"(addr));
    return v;
}
#define CLUSTER_SYNC() do { \
    asm volatile("barrier.cluster.arrive.aligned;" ::: "memory"); \
    asm volatile("barrier.cluster.wait.aligned;"  ::: "memory"); } while (0)

// ---------------- Stage A: 2-CTA cluster, 1024 thr, 2 CTA/SM ---------------
// smem (floats): A 64x132 | Bx 80x132 (rows e<->global 64h+e-8) | pad 20 | C 64x132
#define A_OFF  0
#define BX_OFF 8448                         // 64*132
#define C_OFF  19028                        // BX_OFF + 80*132 + 20  (==20 mod 32)
#define SMA_FLOATS (19028 + 8448)
#define SMA_BYTES  (SMA_FLOATS * 4)         // 109,904 B -> 2 CTAs/SM

// Row conv, chunk-consumed (reg-light): out col 8s+m = sum_u FILT[u]*S[8s+m+u-OFF]
// window e=0..23 <-> src col 8s-8+e; tap index u = e - m - (8-OFF).
template <int OFF>
__device__ __forceinline__ void rowconvA2(const float* __restrict__ srow,
                                          float* __restrict__ drow, int s)
{
    DEF_FILT;
    float acc[8];
    #pragma unroll
    for (int m = 0; m < 8; ++m) acc[m] = 0.f;
    const int cbase = 8 * s - 8;
    #pragma unroll
    for (int v = 0; v < 6; ++v) {
        float tv[4];
        if (s >= 1 && s <= 14) {
            const float4 t = *(const float4*)(srow + cbase + 4 * v);
            tv[0]=t.x; tv[1]=t.y; tv[2]=t.z; tv[3]=t.w;
        } else {
            #pragma unroll
            for (int x = 0; x < 4; ++x)
                tv[x] = srow[(cbase + 4 * v + x) & 127];
        }
        #pragma unroll
        for (int x = 0; x < 4; ++x) {
            const int e = 4 * v + x;
            #pragma unroll
            for (int m = 0; m < 8; ++m) {
                const int u = e - m - (8 - OFF);
                if (u >= 0 && u < 12) acc[m] = fmaf(FILT[u], tv[x], acc[m]);
            }
        }
    }
    float4 o0, o1;
    o0.x=acc[0]; o0.y=acc[1]; o0.z=acc[2]; o0.w=acc[3];
    o1.x=acc[4]; o1.y=acc[5]; o1.z=acc[6]; o1.w=acc[7];
    *(float4*)(drow + 8 * s)     = o0;
    *(float4*)(drow + 8 * s + 4) = o1;
}

// Column conv over extended Bx, 2 rows x 4 cols per thread (1024 thr exact).
// MODE 0: C = -1/sqrt2*(Y1 + conv);  MODE 1: A = sqrt2*A + conv.
template <int OFF, int MODE>
__device__ __forceinline__ void colconvA2(const float* __restrict__ Bx,
                                          float* __restrict__ Dst,
                                          const float* __restrict__ gy,
                                          int tid)
{
    DEF_FILT;
    const int cg = tid & 31;                // 32 f4 groups (128 cols)
    const int rl = (tid >> 5) * 2;          // local rows rl, rl+1
    float4 a0 = {0,0,0,0}, a1 = {0,0,0,0};
    #pragma unroll
    for (int kk = 0; kk < 13; ++kk) {
        const float4 v = *(const float4*)(Bx + (rl + kk - OFF + 8) * PA + 4 * cg);
        if (kk <= 11) a0 = f4fma(FILT[kk],     v, a0);
        if (kk >= 1)  a1 = f4fma(FILT[kk - 1], v, a1);
    }
    float* d0 = Dst + rl * PA + 4 * cg;
    float* d1 = Dst + (rl + 1) * PA + 4 * cg;
    if (MODE == 0) {
        const float4 xa = *(const float4*)(gy + rl * 128 + 4 * cg);
        const float4 xb = *(const float4*)(gy + (rl + 1) * 128 + 4 * cg);
        float4 o0, o1;
        o0.x = -INV_SQRT2 * (xa.x + a0.x); o0.y = -INV_SQRT2 * (xa.y + a0.y);
        o0.z = -INV_SQRT2 * (xa.z + a0.z); o0.w = -INV_SQRT2 * (xa.w + a0.w);
        o1.x = -INV_SQRT2 * (xb.x + a1.x); o1.y = -INV_SQRT2 * (xb.y + a1.y);
        o1.z = -INV_SQRT2 * (xb.z + a1.z); o1.w = -INV_SQRT2 * (xb.w + a1.w);
        *(float4*)d0 = o0; *(float4*)d1 = o1;
    } else {
        const float4 xa = *(const float4*)d0;
        const float4 xb = *(const float4*)d1;
        float4 o0, o1;
        o0.x = SQRT2 * xa.x + a0.x; o0.y = SQRT2 * xa.y + a0.y;
        o0.z = SQRT2 * xa.z + a0.z; o0.w = SQRT2 * xa.w + a0.w;
        o1.x = SQRT2 * xb.x + a1.x; o1.y = SQRT2 * xb.y + a1.y;
        o1.z = SQRT2 * xb.z + a1.z; o1.w = SQRT2 * xb.w + a1.w;
        *(float4*)d0 = o0; *(float4*)d1 = o1;
    }
}

// Copy the 12 halo rows (e in {2..7} u {72..77}) from peer Bx via DSMEM.
__device__ __forceinline__ void haloA2(float* __restrict__ Bx,
                                       uint32_t peerBx, int h,
                                       int wrp, int lane)
{
    if (wrp < 12) {
        const int e  = (wrp < 6) ? (2 + wrp) : (66 + wrp);   // 2..7, 72..77
        const int ge = (64 * h + e - 8) & 127;
        const int ep = (ge & 63) + 8;                        // peer extended row
        const uint32_t pb = peerBx + (uint32_t)(ep * PA) * 4u;
        float* dst = Bx + e * PA;
        #pragma unroll
        for (int c4 = 0; c4 < 4; ++c4)
            dst[lane + 32 * c4] = ld_dsm(pb + (uint32_t)(lane + 32 * c4) * 4u);
    }
}

__global__ __launch_bounds__(1024, 2) __cluster_dims__(2, 1, 1)
void stageA_kernel(const float* __restrict__ y0, const float* __restrict__ y1,
                   const float* __restrict__ y2, const float* __restrict__ y3)
{
    extern __shared__ float smA[];
    float* A  = smA + A_OFF;
    float* Bx = smA + BX_OFF;
    float* C  = smA + C_OFF;

    const int tid  = threadIdx.x;
    const int lane = tid & 31;
    const int wrp  = tid >> 5;
    uint32_t hr;
    asm("mov.u32 %0, %%cluster_ctarank;" : "=r"(hr));
    const int h   = (int)hr;                 // owns global rows [64h, 64h+64)
    const int img = blockIdx.x >> 1;
    const int b = img >> 6, ch = img & 63;
    const float* gY0;
    const float* gY1;
    if (ch < 32) { gY0 = y1 + (b * 32 + ch) * 16384;
                   gY1 = y0 + (b * 32 + ch) * 16384; }
    else         { gY0 = y2 + (b * 32 + ch - 32) * 16384;
                   gY1 = y3 + (b * 32 + ch - 32) * 16384; }
    const float* gY0r = gY0 + 64 * h * 128;
    const float* gY1r = gY1 + 64 * h * 128;

    const uint32_t peerBx = mapa_rank(smem_u32(Bx), hr ^ 1u);

    // load Y0 local rows (f4, coalesced)
    #pragma unroll
    for (int idx = tid; idx < 2048; idx += 1024) {
        const int i = idx >> 5, g = idx & 31;
        *(float4*)(A + i * PA + 4 * g) = *(const float4*)(gY0r + i * 128 + 4 * g);
    }
    __syncthreads();

    // rowconv(Y0, off 5) -> Bx local rows
    {
        const int s = lane & 15, half = lane >> 4;
        const int r = 2 * wrp + half;
        rowconvA2<5>(A + r * PA, Bx + (r + 8) * PA, s);
    }
    __syncthreads();
    CLUSTER_SYNC();                 // both CTAs' Bx local rows complete
    haloA2(Bx, peerBx, h, wrp, lane);
    __syncthreads();
    CLUSTER_SYNC();                 // halo reads done before Bx is rewritten

    // colconv -> C = p1
    colconvA2<5, 0>(Bx, C, gY1r, tid);
    __syncthreads();

    // rowconv(p1, off 6) -> Bx local rows
    {
        const int s = lane & 15, half = lane >> 4;
        const int r = 2 * wrp + half;
        rowconvA2<6>(C + r * PA, Bx + (r + 8) * PA, s);
    }
    __syncthreads();
    CLUSTER_SYNC();
    haloA2(Bx, peerBx, h, wrp, lane);
    __syncthreads();
    CLUSTER_SYNC();

    // colconv -> A = p0 = sqrt2*Y0 + conv
    colconvA2<6, 1>(Bx, A, nullptr, tid);
    __syncthreads();

    // qprec '2c': CTA h writes, per output row i, the contiguous j-window
    // [(i-128h-127)&255 .. (i-128h)&255]; all sources are LOCAL rows.
    {
        float* gx = g_x + img * 32768;
        const int seg   = wrp & 3;
        const int ib    = wrp >> 2;            // 0..7
        const int joff0 = 32 * seg + lane;     // 0..127
        #pragma unroll 4
        for (int it = 0; it < 16; ++it) {
            const int i = it * 8 + ib;
            const int j = (i - 128 * h - 127 + joff0) & 255;
            const int col = (i + j) & 255;
            const int t = col >> 1;
            float v;
            if (col & 1) v = C[(((i - 1 - t) & 127) - 64 * h) * PA + t];
            else         v = A[(((i - t) & 127) - 64 * h) * PA + t];
            gx[i * 256 + j] = v;
        }
    }
    CLUSTER_SYNC();                 // keep smem alive for any in-flight peer ops
}

// ---------------- Fused Stage B + qprec (4-CTA cluster, 2 CTA/SM) ----------
// EXACT R13 version (67.0us).

#define QP  264
#define EP  268
#define Q0OFF 0
#define Q1OFF 8464
#define EOFF  16912
#define SMB_FLOATS (16912 + 43 * 268)
#define SMB_BYTES (SMB_FLOATS * 4)  // 113,744 B -> 2 CTAs/SM

__device__ __forceinline__ void rowconv_inplace(float* __restrict__ erow,
                                                int lane)
{
    DEF_FILT;
    const float* tr = erow + 8 * lane;
    float acc[8];
    #pragma unroll
    for (int m = 0; m < 8; ++m) acc[m] = 0.f;
    #pragma unroll
    for (int v = 0; v < 5; ++v) {
        const float4 t = *(const float4*)(tr + 4 * v);
        const float tv[4] = {t.x, t.y, t.z, t.w};
        #pragma unroll
        for (int x = 0; x < 4; ++x) {
            const int e = 4 * v + x;
            #pragma unroll
            for (int m = 0; m < 8; ++m)
                if (e - m >= 0 && e - m < 12)
                    acc[m] = fmaf(FILT[e - m], tv[x], acc[m]);
        }
    }
    __syncwarp();
    float4 o0, o1;
    o0.x=acc[0]; o0.y=acc[1]; o0.z=acc[2]; o0.w=acc[3];
    o1.x=acc[4]; o1.y=acc[5]; o1.z=acc[6]; o1.w=acc[7];
    *(float4*)(erow + 8 * lane)     = o0;
    *(float4*)(erow + 8 * lane + 4) = o1;
}

__global__ __launch_bounds__(1024, 2) __cluster_dims__(4, 1, 1)
void stageB_fused(float* __restrict__ out)
{
    extern __shared__ float smB[];
    float* Q0 = smB + Q0OFF;
    float* Q1 = smB + Q1OFF;
    float* E  = smB + EOFF;

    const int tid  = threadIdx.x;
    const int lane = tid & 31;
    const int wrp  = tid >> 5;
    uint32_t qr;
    asm("mov.u32 %0, %%cluster_ctarank;" : "=r"(qr));
    const int q    = (int)qr;
    const int img2 = blockIdx.x >> 2;
    const int x0base = ((img2 >> 5) * 64 + (img2 & 31)) * 32768;
    const float* x0g = g_x + x0base;
    const float* x1g = x0g + 32 * 32768;

    const uint32_t q1Local = smem_u32(Q1);

    DEF_FILT;

    // ==== phase 1 ====
    {
        const int rowbase = 32 * q - 5;
        for (int k = wrp; k < 43; k += 32) {
            int gr = rowbase + k;
            int flip = 0;
            if (gr < 0)         { gr += 128; flip = 128; }
            else if (gr >= 128) { gr -= 128; flip = 128; }
            const float* srow = x0g + gr * 256;
            float* erow = E + k * EP;
            for (int c = lane; c < 267; c += 32)
                erow[c] = srow[((c - 5) & 255) ^ flip];
            __syncwarp();
            rowconv_inplace(erow, lane);
        }
        __syncthreads();

        {
            const int cg = tid & 63;
            const int rs = (tid >> 6) * 2;
            float4 acc0 = {0,0,0,0}, acc1 = {0,0,0,0};
            #pragma unroll
            for (int k = 0; k < 13; ++k) {
                const float4 v = *(const float4*)(E + (rs + k) * EP + 4 * cg);
                if (k <= 11) acc0 = f4fma(FILT[k],     v, acc0);
                if (k >= 1)  acc1 = f4fma(FILT[k - 1], v, acc1);
            }
            const int gi = 32 * q + rs;
            const float4 xa = *(const float4*)(x1g + gi * 256 + 4 * cg);
            const float4 xb = *(const float4*)(x1g + (gi + 1) * 256 + 4 * cg);
            float4 o0, o1;
            o0.x = -INV_SQRT2 * (xa.x + acc0.x);
            o0.y = -INV_SQRT2 * (xa.y + acc0.y);
            o0.z = -INV_SQRT2 * (xa.z + acc0.z);
            o0.w = -INV_SQRT2 * (xa.w + acc0.w);
            o1.x = -INV_SQRT2 * (xb.x + acc1.x);
            o1.y = -INV_SQRT2 * (xb.y + acc1.y);
            o1.z = -INV_SQRT2 * (xb.z + acc1.z);
            o1.w = -INV_SQRT2 * (xb.w + acc1.w);
            *(float4*)(Q1 + rs * QP + 4 * cg)       = o0;
            *(float4*)(Q1 + (rs + 1) * QP + 4 * cg) = o1;
        }
    }

    CLUSTER_SYNC();

    // ==== phase 2 ====
    {
        const int rowbase = 32 * q - 6;
        for (int k = wrp; k < 43; k += 32) {
            int gr = rowbase + k;
            int flip = 0;
            if (gr < 0)         { gr += 128; flip = 128; }
            else if (gr >= 128) { gr -= 128; flip = 128; }
            const int owner = gr >> 5;
            const int lr    = gr & 31;
            float* erow = E + k * EP;
            if (owner == q) {
                const float* qrow = Q1 + lr * QP;
                for (int c = lane; c < 267; c += 32)
                    erow[c] = qrow[((c - 6) & 255) ^ flip];
            } else {
                const uint32_t pb = mapa_rank(q1Local, (uint32_t)owner)
                                  + (uint32_t)(lr * QP) * 4u;
                for (int c = lane; c < 267; c += 32)
                    erow[c] = ld_dsm(pb + (uint32_t)(((c - 6) & 255) ^ flip) * 4u);
            }
            __syncwarp();
            rowconv_inplace(erow, lane);
        }
        __syncthreads();

        {
            const int cg = tid & 63;
            const int rs = (tid >> 6) * 2;
            float4 acc0 = {0,0,0,0}, acc1 = {0,0,0,0};
            #pragma unroll
            for (int k = 0; k < 13; ++k) {
                const float4 v = *(const float4*)(E + (rs + k) * EP + 4 * cg);
                if (k <= 11) acc0 = f4fma(FILT[k],     v, acc0);
                if (k >= 1)  acc1 = f4fma(FILT[k - 1], v, acc1);
            }
            const int gi = 32 * q + rs;
            const float4 xa = *(const float4*)(x0g + gi * 256 + 4 * cg);
            const float4 xb = *(const float4*)(x0g + (gi + 1) * 256 + 4 * cg);
            float4 o0, o1;
            o0.x = SQRT2 * xa.x + acc0.x;
            o0.y = SQRT2 * xa.y + acc0.y;
            o0.z = SQRT2 * xa.z + acc0.z;
            o0.w = SQRT2 * xa.w + acc0.w;
            o1.x = SQRT2 * xb.x + acc1.x;
            o1.y = SQRT2 * xb.y + acc1.y;
            o1.z = SQRT2 * xb.z + acc1.z;
            o1.w = SQRT2 * xb.w + acc1.w;
            *(float4*)(Q0 + rs * QP + 4 * cg)       = o0;
            *(float4*)(Q0 + (rs + 1) * QP + 4 * cg) = o1;
        }
        __syncthreads();
    }

    // ==== phase 3 ====
    {
        float* og = out + img2 * 65536;
        const int base64 = 64 * q;
        #pragma unroll
        for (int p = 0; p < 2; ++p) {
            const int row = base64 + 32 * p + lane;
            const int r   = row >> 1;
            const int lr  = (32 * p + lane) >> 1;
            const float* src = (lane & 1) ? (Q1 + lr * QP) : (Q0 + lr * QP);
            const int coff = (lane & 1) ? (-1 - r) : (-r);
            #pragma unroll
            for (int ui = 0; ui < 8; ++ui) {
                const int u = (wrp << 3) + ui;
                const int j = (base64 - u + 32 * p + lane) & 255;
                og[u * 256 + j] = src[(j + coff) & 255];
            }
        }
    }

    CLUSTER_SYNC();
}

// ---------------------------------------------------------------------------

extern "C" void kernel_launch(void* const* d_in, const int* in_sizes, int n_in,
                              void* d_out, int out_size)
{
    const float* y0 = (const float*)d_in[0];
    const float* y1 = (const float*)d_in[1];
    const float* y2 = (const float*)d_in[2];
    const float* y3 = (const float*)d_in[3];

    static bool once = []() {
        cudaFuncSetAttribute(stageA_kernel,
                             cudaFuncAttributeMaxDynamicSharedMemorySize,
                             SMA_BYTES);
        cudaFuncSetAttribute(stageB_fused,
                             cudaFuncAttributeMaxDynamicSharedMemorySize,
                             SMB_BYTES);
        return true;
    }();
    (void)once;

    stageA_kernel<<<1024, 1024, SMA_BYTES>>>(y0, y1, y2, y3);
    stageB_fused<<<1024, 1024, SMB_BYTES>>>((float*)d_out);
}